// round 1
// baseline (speedup 1.0000x reference)
#include <cuda_runtime.h>
#include <math.h>

#define BB 4
#define SS 2048
#define EE 768
#define HH 12
#define DD 64

// Scratch (static device globals: no allocation allowed)
__device__ float g_q[(size_t)BB * HH * SS * DD];
__device__ float g_k[(size_t)BB * HH * SS * DD];
__device__ float g_v[(size_t)BB * HH * SS * DD];
__device__ float g_y[(size_t)BB * SS * EE];

// ---------------------------------------------------------------------------
// Tiled SGEMM: C[M,N] = A[M,K] @ W[K,N] + bias[N]
// MODE 0: plain write to C
// MODE 1: QKV scatter epilogue into g_q/g_k/g_v laid out [B,H,S,D]
// MODE 2: A is ignored; reads from g_y (avoids cudaGetSymbolAddress)
// Tile 64x64, BK=16, 256 threads, 4x4 per-thread register tile.
// ---------------------------------------------------------------------------
template <int MODE>
__global__ __launch_bounds__(256) void gemm64(const float* __restrict__ A,
                                              const float* __restrict__ W,
                                              const float* __restrict__ bias,
                                              float* __restrict__ C,
                                              int M, int N, int K) {
    __shared__ float As[16][68];  // transposed: As[k][m]
    __shared__ float Bs[16][68];

    const float* Aptr = (MODE == 2) ? (const float*)g_y : A;

    const int tid = threadIdx.x;
    const int tx = tid & 15;   // n-group
    const int ty = tid >> 4;   // m-group
    const int bm = blockIdx.y * 64;
    const int bn = blockIdx.x * 64;

    float acc[4][4];
#pragma unroll
    for (int i = 0; i < 4; i++)
#pragma unroll
        for (int j = 0; j < 4; j++) acc[i][j] = 0.f;

    const int lr = tid >> 2;          // 0..63 (A tile row)
    const int lc = (tid & 3) << 2;    // 0,4,8,12 (A tile col)
    const int bj = tid << 2;          // 0..1020
    const int br = bj >> 6;           // 0..15 (B tile row)
    const int bc = bj & 63;           // B tile col

    for (int k0 = 0; k0 < K; k0 += 16) {
        float4 av = *(const float4*)&Aptr[(size_t)(bm + lr) * K + k0 + lc];
        As[lc + 0][lr] = av.x;
        As[lc + 1][lr] = av.y;
        As[lc + 2][lr] = av.z;
        As[lc + 3][lr] = av.w;
        float4 bv = *(const float4*)&W[(size_t)(k0 + br) * N + bn + bc];
        *(float4*)&Bs[br][bc] = bv;
        __syncthreads();
#pragma unroll
        for (int kk = 0; kk < 16; kk++) {
            float4 a = *(const float4*)&As[kk][ty << 2];
            float4 b = *(const float4*)&Bs[kk][tx << 2];
            acc[0][0] += a.x * b.x; acc[0][1] += a.x * b.y; acc[0][2] += a.x * b.z; acc[0][3] += a.x * b.w;
            acc[1][0] += a.y * b.x; acc[1][1] += a.y * b.y; acc[1][2] += a.y * b.z; acc[1][3] += a.y * b.w;
            acc[2][0] += a.z * b.x; acc[2][1] += a.z * b.y; acc[2][2] += a.z * b.z; acc[2][3] += a.z * b.w;
            acc[3][0] += a.w * b.x; acc[3][1] += a.w * b.y; acc[3][2] += a.w * b.z; acc[3][3] += a.w * b.w;
        }
        __syncthreads();
    }

    if (MODE == 0 || MODE == 2) {
        float4 bv = *(const float4*)&bias[bn + (tx << 2)];
#pragma unroll
        for (int i = 0; i < 4; i++) {
            int row = bm + (ty << 2) + i;
            float4 o;
            o.x = acc[i][0] + bv.x;
            o.y = acc[i][1] + bv.y;
            o.z = acc[i][2] + bv.z;
            o.w = acc[i][3] + bv.w;
            *(float4*)&C[(size_t)row * N + bn + (tx << 2)] = o;
        }
    } else {
        // QKV scatter: row = b*S+s; n -> (sec, h, d)
#pragma unroll
        for (int i = 0; i < 4; i++) {
            int row = bm + (ty << 2) + i;
            int b = row >> 11;  // / 2048
            int s = row & 2047;
#pragma unroll
            for (int j = 0; j < 4; j++) {
                int n = bn + (tx << 2) + j;
                int sec = n / EE;
                int e = n - sec * EE;
                int h = e >> 6;
                int d = e & 63;
                float val = acc[i][j] + bias[n];
                float* dst = (sec == 0) ? g_q : ((sec == 1) ? g_k : g_v);
                dst[(((size_t)b * HH + h) * SS + s) * DD + d] = val;
            }
        }
    }
}

// ---------------------------------------------------------------------------
// Flash attention (fp32, causal + att_mask), 64-query tiles.
// Block: 256 threads = 64 q-rows x 4 col-threads (c).
// Thread (q,c): scores for keys k = 4*i + c (interleaved -> conflict-free),
//               output dims d = 16*jj + 4*c + t (interleaved float4 chunks).
// ---------------------------------------------------------------------------
#define ATTN_SMEM_FLOATS (4 * 64 * 68 + 64)
#define ATTN_SMEM_BYTES (ATTN_SMEM_FLOATS * 4)

__global__ __launch_bounds__(256) void attn_kernel(const int* __restrict__ att_mask) {
    extern __shared__ float sm[];
    float* Qs = sm;
    float* Ks = sm + 64 * 68;
    float* Vs = sm + 2 * 64 * 68;
    float* Ps = sm + 3 * 64 * 68;
    int* msk = (int*)(sm + 4 * 64 * 68);

    const int qt = blockIdx.x;   // 0..31
    const int bh = blockIdx.y;   // 0..47
    const int b = bh / HH;
    const int h = bh % HH;
    const int tid = threadIdx.x;
    const int q = tid >> 2;  // 0..63
    const int c = tid & 3;   // 0..3

    const float* qptr = g_q + (size_t)bh * SS * DD;
    const float* kptr = g_k + (size_t)bh * SS * DD;
    const float* vptr = g_v + (size_t)bh * SS * DD;

    // Load Q tile (64x64) into smem
#pragma unroll
    for (int i = 0; i < 4; i++) {
        int j = tid + i * 256;  // float4 index 0..1023
        int r = j >> 4;
        int c4 = (j & 15) << 2;
        *(float4*)&Qs[r * 68 + c4] = *(const float4*)&qptr[(qt * 64 + r) * 64 + c4];
    }

    float4 o4[4];
#pragma unroll
    for (int jj = 0; jj < 4; jj++) o4[jj] = make_float4(0.f, 0.f, 0.f, 0.f);
    float m = -1e30f, l = 0.f;

    const int qg = qt * 64 + q;

    for (int kt = 0; kt <= qt; kt++) {
        // Load K,V tiles + mask slice
#pragma unroll
        for (int i = 0; i < 4; i++) {
            int j = tid + i * 256;
            int r = j >> 4;
            int c4 = (j & 15) << 2;
            *(float4*)&Ks[r * 68 + c4] = *(const float4*)&kptr[(kt * 64 + r) * 64 + c4];
            *(float4*)&Vs[r * 68 + c4] = *(const float4*)&vptr[(kt * 64 + r) * 64 + c4];
        }
        if (tid < 64) msk[tid] = att_mask[b * SS + kt * 64 + tid];
        __syncthreads();

        // Scores: thread handles keys k = 4*i + c
        float s[16];
#pragma unroll
        for (int i = 0; i < 16; i++) s[i] = 0.f;
#pragma unroll 4
        for (int d4 = 0; d4 < 16; d4++) {
            float4 qv = *(const float4*)&Qs[q * 68 + (d4 << 2)];
#pragma unroll
            for (int i = 0; i < 16; i++) {
                float4 kv = *(const float4*)&Ks[(4 * i + c) * 68 + (d4 << 2)];
                s[i] += qv.x * kv.x + qv.y * kv.y + qv.z * kv.z + qv.w * kv.w;
            }
        }

        // Mask + scale + local max
        float lm = -1e30f;
#pragma unroll
        for (int i = 0; i < 16; i++) {
            int kl = 4 * i + c;
            int kg = kt * 64 + kl;
            bool valid = (kg <= qg) && (msk[kl] != 0);
            s[i] = valid ? s[i] * 0.125f : -1e30f;
            lm = fmaxf(lm, s[i]);
        }
        // Row reduction across the 4 threads of this q row (same warp)
        lm = fmaxf(lm, __shfl_xor_sync(0xffffffffu, lm, 1));
        lm = fmaxf(lm, __shfl_xor_sync(0xffffffffu, lm, 2));
        float mnew = fmaxf(m, lm);
        float alpha = __expf(m - mnew);
        float ls = 0.f;
#pragma unroll
        for (int i = 0; i < 16; i++) {
            float p = __expf(s[i] - mnew);
            Ps[q * 68 + 4 * i + c] = p;
            ls += p;
        }
        ls += __shfl_xor_sync(0xffffffffu, ls, 1);
        ls += __shfl_xor_sync(0xffffffffu, ls, 2);
        l = l * alpha + ls;
        m = mnew;
#pragma unroll
        for (int jj = 0; jj < 4; jj++) {
            o4[jj].x *= alpha; o4[jj].y *= alpha; o4[jj].z *= alpha; o4[jj].w *= alpha;
        }
        __syncwarp();  // Ps written by the 4 threads of this row (same warp)

        // PV: o[d] += sum_k P[q,k] * V[k,d]; thread's d chunks at 16*jj + 4*c
#pragma unroll 8
        for (int k = 0; k < 64; k++) {
            float p = Ps[q * 68 + k];
#pragma unroll
            for (int jj = 0; jj < 4; jj++) {
                float4 v = *(const float4*)&Vs[k * 68 + (jj << 4) + (c << 2)];
                o4[jj].x += p * v.x;
                o4[jj].y += p * v.y;
                o4[jj].z += p * v.z;
                o4[jj].w += p * v.w;
            }
        }
        __syncthreads();  // protect Ks/Vs/Ps before next tile's loads
    }

    float inv = 1.f / l;
    float* yout = g_y + ((size_t)b * SS + qg) * EE + h * 64;
#pragma unroll
    for (int jj = 0; jj < 4; jj++) {
        float4 r;
        r.x = o4[jj].x * inv;
        r.y = o4[jj].y * inv;
        r.z = o4[jj].z * inv;
        r.w = o4[jj].w * inv;
        *(float4*)&yout[(jj << 4) + (c << 2)] = r;
    }
}

// ---------------------------------------------------------------------------
extern "C" void kernel_launch(void* const* d_in, const int* in_sizes, int n_in,
                              void* d_out, int out_size) {
    // Identify inputs by element count (all six are distinct)
    const float* x = nullptr;
    const float* W_attn = nullptr;
    const float* b_attn = nullptr;
    const float* W_proj = nullptr;
    const float* b_proj = nullptr;
    const int* att_mask = nullptr;
    for (int i = 0; i < n_in; i++) {
        switch (in_sizes[i]) {
            case BB * SS * EE:   x = (const float*)d_in[i]; break;       // 6291456
            case EE * 3 * EE:    W_attn = (const float*)d_in[i]; break;  // 1769472
            case 3 * EE:         b_attn = (const float*)d_in[i]; break;  // 2304
            case EE * EE:        W_proj = (const float*)d_in[i]; break;  // 589824
            case EE:             b_proj = (const float*)d_in[i]; break;  // 768
            case BB * SS:        att_mask = (const int*)d_in[i]; break;  // 8192
            default: break;
        }
    }
    float* out = (float*)d_out;

    // 1) QKV GEMM + scatter into [B,H,S,D]
    gemm64<1><<<dim3(3 * EE / 64, BB * SS / 64), 256>>>(x, W_attn, b_attn, nullptr,
                                                        BB * SS, 3 * EE, EE);

    // 2) Flash attention
    cudaFuncSetAttribute(attn_kernel, cudaFuncAttributeMaxDynamicSharedMemorySize,
                         ATTN_SMEM_BYTES);
    attn_kernel<<<dim3(SS / 64, BB * HH), 256, ATTN_SMEM_BYTES>>>(att_mask);

    // 3) Projection GEMM (reads g_y internally, MODE 2)
    gemm64<2><<<dim3(EE / 64, BB * SS / 64), 256>>>(nullptr, W_proj, b_proj, out,
                                                    BB * SS, EE, EE);
}

// round 2
// speedup vs baseline: 1.7175x; 1.7175x over previous
#include <cuda_runtime.h>
#include <math.h>

#define BB 4
#define SS 2048
#define EE 768
#define HH 12
#define DD 64

// Scratch (static device globals: no allocation allowed)
__device__ float g_q[(size_t)BB * HH * SS * DD];
__device__ float g_k[(size_t)BB * HH * SS * DD];
__device__ float g_v[(size_t)BB * HH * SS * DD];
__device__ float g_y[(size_t)BB * SS * EE];

// Fast exp2 on FMA pipe (valid for x <= ~1; clamps at -126 -> ~0)
__device__ __forceinline__ float fexp2(float x) {
    x = fmaxf(x, -126.f);
    float z = x + 12582912.f;                 // round-to-nearest-int magic
    int n = __float_as_int(z) - 0x4B400000;   // integer part
    float fi = z - 12582912.f;
    float f = x - fi;                         // f in [-0.5, 0.5]
    float r = 1.3333558146e-3f;               // ln2^5/120
    r = fmaf(r, f, 9.6181291e-3f);            // ln2^4/24
    r = fmaf(r, f, 5.5504108664e-2f);         // ln2^3/6
    r = fmaf(r, f, 2.4022650695910e-1f);      // ln2^2/2
    r = fmaf(r, f, 6.9314718055995e-1f);      // ln2
    r = fmaf(r, f, 1.0f);
    return r * __int_as_float((n + 127) << 23);
}

// ---------------------------------------------------------------------------
// SGEMM 128x128 tile, BK=8, 256 threads, 8x8 per-thread, double-buffered.
// MODE 0: C = A@W + bias
// MODE 1: QKV scatter epilogue into g_q/g_k/g_v [B,H,S,D]
// MODE 2: A := g_y
// ---------------------------------------------------------------------------
template <int MODE>
__global__ __launch_bounds__(256, 2) void gemm128(const float* __restrict__ A,
                                                  const float* __restrict__ W,
                                                  const float* __restrict__ bias,
                                                  float* __restrict__ C,
                                                  int M, int N, int K) {
    __shared__ float As[2][8][132];  // As[buf][k][m] (transposed)
    __shared__ float Bs[2][8][132];  // Bs[buf][k][n]

    const float* Aptr = (MODE == 2) ? (const float*)g_y : A;

    const int tid = threadIdx.x;
    const int tx = tid & 15;
    const int ty = tid >> 4;
    const int bm = blockIdx.y * 128;
    const int bn = blockIdx.x * 128;

    const int ar = tid >> 1;          // A tile row 0..127
    const int ac = (tid & 1) << 2;    // A tile col 0 or 4
    const int br = tid >> 5;          // B tile row 0..7
    const int bc = (tid & 31) << 2;   // B tile col

    const float* Arow = Aptr + (size_t)(bm + ar) * K + ac;
    const float* Brow = W + (size_t)br * N + bn + bc;

    float acc[8][8];
#pragma unroll
    for (int i = 0; i < 8; i++)
#pragma unroll
        for (int j = 0; j < 8; j++) acc[i][j] = 0.f;

    float4 pa = *(const float4*)Arow;
    float4 pb = *(const float4*)Brow;
    As[0][ac + 0][ar] = pa.x;
    As[0][ac + 1][ar] = pa.y;
    As[0][ac + 2][ar] = pa.z;
    As[0][ac + 3][ar] = pa.w;
    *(float4*)&Bs[0][br][bc] = pb;
    __syncthreads();

    int cur = 0;
    for (int k0 = 0; k0 < K; k0 += 8) {
        const bool more = (k0 + 8) < K;
        if (more) {
            pa = *(const float4*)(Arow + k0 + 8);
            pb = *(const float4*)(Brow + (size_t)(k0 + 8) * N);
        }
#pragma unroll
        for (int kk = 0; kk < 8; kk++) {
            float a[8], b[8];
            *(float4*)&a[0] = *(const float4*)&As[cur][kk][ty << 2];
            *(float4*)&a[4] = *(const float4*)&As[cur][kk][64 + (ty << 2)];
            *(float4*)&b[0] = *(const float4*)&Bs[cur][kk][tx << 2];
            *(float4*)&b[4] = *(const float4*)&Bs[cur][kk][64 + (tx << 2)];
#pragma unroll
            for (int i = 0; i < 8; i++)
#pragma unroll
                for (int j = 0; j < 8; j++) acc[i][j] = fmaf(a[i], b[j], acc[i][j]);
        }
        if (more) {
            const int nxt = cur ^ 1;
            As[nxt][ac + 0][ar] = pa.x;
            As[nxt][ac + 1][ar] = pa.y;
            As[nxt][ac + 2][ar] = pa.z;
            As[nxt][ac + 3][ar] = pa.w;
            *(float4*)&Bs[nxt][br][bc] = pb;
            __syncthreads();
            cur = nxt;
        }
    }

    if (MODE == 0 || MODE == 2) {
        float4 bv0 = *(const float4*)&bias[bn + (tx << 2)];
        float4 bv1 = *(const float4*)&bias[bn + 64 + (tx << 2)];
#pragma unroll
        for (int ih = 0; ih < 2; ih++) {
#pragma unroll
            for (int i = 0; i < 4; i++) {
                int row = bm + ih * 64 + (ty << 2) + i;
                int ai = ih * 4 + i;
                float4 o0, o1;
                o0.x = acc[ai][0] + bv0.x; o0.y = acc[ai][1] + bv0.y;
                o0.z = acc[ai][2] + bv0.z; o0.w = acc[ai][3] + bv0.w;
                o1.x = acc[ai][4] + bv1.x; o1.y = acc[ai][5] + bv1.y;
                o1.z = acc[ai][6] + bv1.z; o1.w = acc[ai][7] + bv1.w;
                *(float4*)&C[(size_t)row * N + bn + (tx << 2)] = o0;
                *(float4*)&C[(size_t)row * N + bn + 64 + (tx << 2)] = o1;
            }
        }
    } else {
#pragma unroll
        for (int ih = 0; ih < 2; ih++) {
#pragma unroll
            for (int i = 0; i < 4; i++) {
                int row = bm + ih * 64 + (ty << 2) + i;
                int b = row >> 11;
                int s = row & 2047;
                int ai = ih * 4 + i;
#pragma unroll
                for (int jh = 0; jh < 2; jh++) {
                    int n0 = bn + jh * 64 + (tx << 2);
                    int sec = n0 / EE;
                    int e = n0 - sec * EE;
                    int h = e >> 6;
                    int d = e & 63;
                    float4 bv = *(const float4*)&bias[n0];
                    float4 o;
                    o.x = acc[ai][jh * 4 + 0] + bv.x;
                    o.y = acc[ai][jh * 4 + 1] + bv.y;
                    o.z = acc[ai][jh * 4 + 2] + bv.z;
                    o.w = acc[ai][jh * 4 + 3] + bv.w;
                    float* dst = (sec == 0) ? g_q : ((sec == 1) ? g_k : g_v);
                    *(float4*)&dst[(((size_t)b * HH + h) * SS + s) * DD + d] = o;
                }
            }
        }
    }
}

// ---------------------------------------------------------------------------
// Flash attention: q-tile 128, k-tile 64, 256 threads.
// tx = tid%16 (key groups of 4 / d groups of 4), ty = tid/16 (q groups of 8).
// Scores: 8x4 register tile; PV: 8x4 register tile; exp via FMA polynomial.
// Smem (dynamic): Qs_T[64][132], Ks_T[64][68], Vs[64][68], Ps_T[64][132], msk.
// ---------------------------------------------------------------------------
#define ATTN_SMEM_FLOATS (64 * 132 + 64 * 68 + 64 * 68 + 64 * 132 + 64)
#define ATTN_SMEM_BYTES (ATTN_SMEM_FLOATS * 4)

__global__ __launch_bounds__(256, 2) void attn_kernel(const int* __restrict__ att_mask) {
    extern __shared__ float sm[];
    float* Qs = sm;                    // [d][q] stride 132
    float* Ks = Qs + 64 * 132;         // [d][k] stride 68
    float* Vs = Ks + 64 * 68;          // [k][d] stride 68
    float* Ps = Vs + 64 * 68;          // [k][q] stride 132
    int* msk = (int*)(Ps + 64 * 132);

    const int qt = (int)gridDim.x - 1 - (int)blockIdx.x;  // long blocks first
    const int bh = blockIdx.y;
    const int b = bh / HH;
    const int h = bh % HH;
    const int tid = threadIdx.x;
    const int tx = tid & 15;
    const int ty = tid >> 4;
    const int q0 = qt * 128;

    const float* qptr = g_q + (size_t)bh * SS * DD;
    const float* kptr = g_k + (size_t)bh * SS * DD;
    const float* vptr = g_v + (size_t)bh * SS * DD;

    // Load Q tile transposed: Qs[d][q]
#pragma unroll
    for (int it = 0; it < 8; it++) {
        int j = tid + it * 256;        // float4 index 0..2047
        int q = j >> 4;
        int c4 = (j & 15) << 2;
        float4 v = *(const float4*)&qptr[(size_t)(q0 + q) * 64 + c4];
        Qs[(c4 + 0) * 132 + q] = v.x;
        Qs[(c4 + 1) * 132 + q] = v.y;
        Qs[(c4 + 2) * 132 + q] = v.z;
        Qs[(c4 + 3) * 132 + q] = v.w;
    }

    float o[8][4];
    float m[8], l[8];
#pragma unroll
    for (int i = 0; i < 8; i++) {
        m[i] = -1e30f;
        l[i] = 0.f;
#pragma unroll
        for (int j = 0; j < 4; j++) o[i][j] = 0.f;
    }

    const float SC = 0.125f * 1.4426950408889634f;  // scale * log2(e)
    const int ktmax = 2 * qt + 1;

    for (int kt = 0; kt <= ktmax; kt++) {
        __syncthreads();  // prev PV done with Vs/Ps; Q load visible via next sync
        // Load K transposed + V straight + mask
#pragma unroll
        for (int it = 0; it < 4; it++) {
            int j = tid + it * 256;    // 0..1023
            int r = j >> 4;
            int c4 = (j & 15) << 2;
            float4 kv = *(const float4*)&kptr[(size_t)(kt * 64 + r) * 64 + c4];
            Ks[(c4 + 0) * 68 + r] = kv.x;
            Ks[(c4 + 1) * 68 + r] = kv.y;
            Ks[(c4 + 2) * 68 + r] = kv.z;
            Ks[(c4 + 3) * 68 + r] = kv.w;
            *(float4*)&Vs[r * 68 + c4] = *(const float4*)&vptr[(size_t)(kt * 64 + r) * 64 + c4];
        }
        if (tid < 64) msk[tid] = att_mask[b * SS + kt * 64 + tid];
        __syncthreads();

        // Scores: s[8][4] over d
        float s[8][4];
#pragma unroll
        for (int i = 0; i < 8; i++)
#pragma unroll
            for (int j = 0; j < 4; j++) s[i][j] = 0.f;
#pragma unroll 8
        for (int d = 0; d < 64; d++) {
            float a[8], bb[4];
            *(float4*)&a[0] = *(const float4*)&Qs[d * 132 + (ty << 3)];
            *(float4*)&a[4] = *(const float4*)&Qs[d * 132 + (ty << 3) + 4];
            *(float4*)&bb[0] = *(const float4*)&Ks[d * 68 + (tx << 2)];
#pragma unroll
            for (int i = 0; i < 8; i++)
#pragma unroll
                for (int j = 0; j < 4; j++) s[i][j] = fmaf(a[i], bb[j], s[i][j]);
        }

        // Softmax update (log2 domain)
        const bool tileFull = (kt * 64 + 63) <= q0;
        float tb[4];
#pragma unroll
        for (int j = 0; j < 4; j++) tb[j] = msk[(tx << 2) + j] ? 0.f : -1e30f;

#pragma unroll
        for (int i = 0; i < 8; i++) {
            const int qg = q0 + (ty << 3) + i;
            float lm = -1e30f;
#pragma unroll
            for (int j = 0; j < 4; j++) {
                float t = fmaf(s[i][j], SC, tb[j]);
                if (!tileFull && (kt * 64 + (tx << 2) + j) > qg) t = -1e30f;
                s[i][j] = t;
                lm = fmaxf(lm, t);
            }
            lm = fmaxf(lm, __shfl_xor_sync(0xffffffffu, lm, 1));
            lm = fmaxf(lm, __shfl_xor_sync(0xffffffffu, lm, 2));
            lm = fmaxf(lm, __shfl_xor_sync(0xffffffffu, lm, 4));
            lm = fmaxf(lm, __shfl_xor_sync(0xffffffffu, lm, 8));
            float mn = fmaxf(m[i], lm);
            float alpha = fexp2(m[i] - mn);
            float ls = 0.f;
#pragma unroll
            for (int j = 0; j < 4; j++) {
                float p = fexp2(s[i][j] - mn);
                s[i][j] = p;
                ls += p;
            }
            ls += __shfl_xor_sync(0xffffffffu, ls, 1);
            ls += __shfl_xor_sync(0xffffffffu, ls, 2);
            ls += __shfl_xor_sync(0xffffffffu, ls, 4);
            ls += __shfl_xor_sync(0xffffffffu, ls, 8);
            l[i] = l[i] * alpha + ls;
            m[i] = mn;
#pragma unroll
            for (int j = 0; j < 4; j++) o[i][j] *= alpha;
        }

        // Write P transposed: Ps[k][q]
#pragma unroll
        for (int j = 0; j < 4; j++) {
            float4 lo = make_float4(s[0][j], s[1][j], s[2][j], s[3][j]);
            float4 hi = make_float4(s[4][j], s[5][j], s[6][j], s[7][j]);
            *(float4*)&Ps[((tx << 2) + j) * 132 + (ty << 3)] = lo;
            *(float4*)&Ps[((tx << 2) + j) * 132 + (ty << 3) + 4] = hi;
        }
        __syncthreads();

        // PV: o[q 8][d 4] over k
#pragma unroll 8
        for (int k = 0; k < 64; k++) {
            float a[8], bb[4];
            *(float4*)&a[0] = *(const float4*)&Ps[k * 132 + (ty << 3)];
            *(float4*)&a[4] = *(const float4*)&Ps[k * 132 + (ty << 3) + 4];
            *(float4*)&bb[0] = *(const float4*)&Vs[k * 68 + (tx << 2)];
#pragma unroll
            for (int i = 0; i < 8; i++)
#pragma unroll
                for (int j = 0; j < 4; j++) o[i][j] = fmaf(a[i], bb[j], o[i][j]);
        }
    }

    // Epilogue
#pragma unroll
    for (int i = 0; i < 8; i++) {
        float inv = 1.0f / l[i];
        int row = q0 + (ty << 3) + i;
        float4 w;
        w.x = o[i][0] * inv;
        w.y = o[i][1] * inv;
        w.z = o[i][2] * inv;
        w.w = o[i][3] * inv;
        *(float4*)&g_y[((size_t)b * SS + row) * EE + h * 64 + (tx << 2)] = w;
    }
}

// ---------------------------------------------------------------------------
extern "C" void kernel_launch(void* const* d_in, const int* in_sizes, int n_in,
                              void* d_out, int out_size) {
    const float* x = nullptr;
    const float* W_attn = nullptr;
    const float* b_attn = nullptr;
    const float* W_proj = nullptr;
    const float* b_proj = nullptr;
    const int* att_mask = nullptr;
    for (int i = 0; i < n_in; i++) {
        switch (in_sizes[i]) {
            case BB * SS * EE:   x = (const float*)d_in[i]; break;
            case EE * 3 * EE:    W_attn = (const float*)d_in[i]; break;
            case 3 * EE:         b_attn = (const float*)d_in[i]; break;
            case EE * EE:        W_proj = (const float*)d_in[i]; break;
            case EE:             b_proj = (const float*)d_in[i]; break;
            case BB * SS:        att_mask = (const int*)d_in[i]; break;
            default: break;
        }
    }
    float* out = (float*)d_out;

    // 1) QKV GEMM + scatter into [B,H,S,D]
    gemm128<1><<<dim3(3 * EE / 128, BB * SS / 128), 256>>>(x, W_attn, b_attn, nullptr,
                                                           BB * SS, 3 * EE, EE);

    // 2) Flash attention
    static bool attr_set = false;
    if (!attr_set) {
        cudaFuncSetAttribute(attn_kernel, cudaFuncAttributeMaxDynamicSharedMemorySize,
                             ATTN_SMEM_BYTES);
        attr_set = true;
    }
    attn_kernel<<<dim3(SS / 128, BB * HH), 256, ATTN_SMEM_BYTES>>>(att_mask);

    // 3) Projection GEMM (reads g_y internally, MODE 2)
    gemm128<2><<<dim3(EE / 128, BB * SS / 128), 256>>>(nullptr, W_proj, b_proj, out,
                                                       BB * SS, EE, EE);
}

// round 6
// speedup vs baseline: 2.4335x; 1.4169x over previous
#include <cuda_runtime.h>
#include <math.h>
#include <cstdint>

#define BB 4
#define SS 2048
#define EE 768
#define HH 12
#define DD 64
#define GK 768

// Scratch (static device globals: no allocation allowed)
__device__ float g_q[(size_t)BB * HH * SS * DD];
__device__ float g_k[(size_t)BB * HH * SS * DD];
__device__ float g_v[(size_t)BB * HH * SS * DD];
__device__ float g_y[(size_t)BB * SS * EE];

// ======================= helpers ============================================
__device__ __forceinline__ uint32_t smem_u32(const void* p) {
    uint32_t a;
    asm("{ .reg .u64 t; cvta.to.shared.u64 t, %1; cvt.u32.u64 %0, t; }" : "=r"(a) : "l"(p));
    return a;
}
__device__ __forceinline__ void cp16(uint32_t dst, const void* src) {
    asm volatile("cp.async.cg.shared.global [%0], [%1], 16;" :: "r"(dst), "l"(src) : "memory");
}
__device__ __forceinline__ void cp_commit() {
    asm volatile("cp.async.commit_group;" ::: "memory");
}
template <int N>
__device__ __forceinline__ void cp_wait() {
    asm volatile("cp.async.wait_group %0;" :: "n"(N) : "memory");
}
__device__ __forceinline__ uint32_t f2tf32(float x) {
    uint32_t u;
    asm("cvt.rna.tf32.f32 %0, %1;" : "=r"(u) : "f"(x));
    return u;
}
__device__ __forceinline__ void mma_tf32(float* d, uint32_t a0, uint32_t a1, uint32_t a2,
                                         uint32_t a3, uint32_t b0, uint32_t b1) {
    asm volatile(
        "mma.sync.aligned.m16n8k8.row.col.f32.tf32.tf32.f32 "
        "{%0,%1,%2,%3}, {%4,%5,%6,%7}, {%8,%9}, {%0,%1,%2,%3};"
        : "+f"(d[0]), "+f"(d[1]), "+f"(d[2]), "+f"(d[3])
        : "r"(a0), "r"(a1), "r"(a2), "r"(a3), "r"(b0), "r"(b1));
}

// Fast exp2 on FMA pipe
__device__ __forceinline__ float fexp2(float x) {
    x = fmaxf(x, -126.f);
    float z = x + 12582912.f;
    int n = __float_as_int(z) - 0x4B400000;
    float fi = z - 12582912.f;
    float f = x - fi;
    float r = 1.3333558146e-3f;
    r = fmaf(r, f, 9.6181291e-3f);
    r = fmaf(r, f, 5.5504108664e-2f);
    r = fmaf(r, f, 2.4022650695910e-1f);
    r = fmaf(r, f, 6.9314718055995e-1f);
    r = fmaf(r, f, 1.0f);
    return r * __int_as_float((n + 127) << 23);
}

// ======================= tf32 mma.sync GEMM =================================
// C[M,N] = A[M,768] @ W[768,N] + bias. 128x128 tile, BK=32, cp.async double buf.
// 8 warps (2m x 4n), warp tile 64x32, m16n8k8 frags 4x4.
// As [m][36] floats (bank 4g+t, conflict-free), Bs [k][136] (bank 8t+g).
// MODE 0: plain; MODE 1: QKV scatter; MODE 2: A := g_y.
#define ABUF 18432            // 128*36*4
#define BBUF 17408            // 32*136*4
#define STAGE (ABUF + BBUF)   // 35840
#define GEMM_SMEM (2 * STAGE) // 71680

template <int MODE>
__global__ __launch_bounds__(256) void gemm_mma(const float* __restrict__ A_,
                                                const float* __restrict__ W,
                                                const float* __restrict__ bias,
                                                float* __restrict__ C, int N) {
    extern __shared__ char sm[];
    const uint32_t sbase = smem_u32(sm);

    const float* A = (MODE == 2) ? (const float*)g_y : A_;
    const int tid = threadIdx.x;
    const int wid = tid >> 5;
    const int lane = tid & 31;
    const int g = lane >> 2;  // group id
    const int t = lane & 3;   // thread-in-group
    const int bm = blockIdx.y * 128;
    const int bn = blockIdx.x * 128;
    const int wm = (wid >> 2) * 64;
    const int wn = (wid & 3) * 32;

    float acc[4][4][4];
#pragma unroll
    for (int mi = 0; mi < 4; mi++)
#pragma unroll
        for (int ni = 0; ni < 4; ni++)
#pragma unroll
            for (int r = 0; r < 4; r++) acc[mi][ni][r] = 0.f;

    // --- async stage loader ---
    const int am = tid >> 3;           // A row 0..31 step (4 iters cover 128)
    const int ac16 = (tid & 7) << 4;   // A byte col 0..112
    const int bk = tid >> 5;           // B row step
    const int bn16 = (tid & 31) << 4;  // B byte col 0..496

#define ISSUE(s, buf)                                                                   \
    {                                                                                   \
        const int k0_ = (s) * 32;                                                       \
        const uint32_t sa_ = sbase + (buf) * STAGE;                                     \
        const uint32_t sb_ = sa_ + ABUF;                                                \
        _Pragma("unroll") for (int it = 0; it < 4; ++it) {                              \
            const int m_ = am + it * 32;                                                \
            cp16(sa_ + m_ * 144 + ac16, &A[(size_t)(bm + m_) * GK + k0_ + (ac16 >> 2)]);\
            const int k_ = bk + it * 8;                                                 \
            cp16(sb_ + k_ * 544 + bn16, &W[(size_t)(k0_ + k_) * N + bn + (bn16 >> 2)]); \
        }                                                                               \
        cp_commit();                                                                    \
    }

    ISSUE(0, 0);
    ISSUE(1, 1);

    for (int s = 0; s < 24; ++s) {
        const int buf = s & 1;
        if (s == 23) cp_wait<0>(); else cp_wait<1>();
        __syncthreads();

        const float* Af = (const float*)(sm + buf * STAGE);
        const float* Bf = (const float*)(sm + buf * STAGE + ABUF);

#pragma unroll
        for (int ks = 0; ks < 4; ++ks) {
            const int kk = ks * 8 + t;
            uint32_t b0[4], b1[4];
#pragma unroll
            for (int ni = 0; ni < 4; ++ni) {
                b0[ni] = f2tf32(Bf[kk * 136 + wn + ni * 8 + g]);
                b1[ni] = f2tf32(Bf[(kk + 4) * 136 + wn + ni * 8 + g]);
            }
#pragma unroll
            for (int mi = 0; mi < 4; ++mi) {
                const int r = wm + mi * 16 + g;
                uint32_t a0 = f2tf32(Af[r * 36 + kk]);
                uint32_t a1 = f2tf32(Af[(r + 8) * 36 + kk]);
                uint32_t a2 = f2tf32(Af[r * 36 + kk + 4]);
                uint32_t a3 = f2tf32(Af[(r + 8) * 36 + kk + 4]);
#pragma unroll
                for (int ni = 0; ni < 4; ++ni)
                    mma_tf32(acc[mi][ni], a0, a1, a2, a3, b0[ni], b1[ni]);
            }
        }
        __syncthreads();
        if (s + 2 < 24) ISSUE(s + 2, buf);
    }

    // --- epilogue: registers -> global (float2 per c-pair) ---
#pragma unroll
    for (int mi = 0; mi < 4; ++mi) {
#pragma unroll
        for (int ni = 0; ni < 4; ++ni) {
            const int r0 = bm + wm + mi * 16 + g;
            const int c0 = bn + wn + ni * 8 + 2 * t;
            const float bz0 = __ldg(&bias[c0]);
            const float bz1 = __ldg(&bias[c0 + 1]);
            float2 v0 = make_float2(acc[mi][ni][0] + bz0, acc[mi][ni][1] + bz1);
            float2 v1 = make_float2(acc[mi][ni][2] + bz0, acc[mi][ni][3] + bz1);
            if (MODE == 1) {
                const int sec = c0 / EE;
                const int e = c0 - sec * EE;
                const int h = e >> 6, d = e & 63;
                float* dst = (sec == 0) ? g_q : ((sec == 1) ? g_k : g_v);
                {
                    const int b = r0 >> 11, srow = r0 & 2047;
                    *(float2*)&dst[(((size_t)b * HH + h) * SS + srow) * DD + d] = v0;
                }
                {
                    const int r1 = r0 + 8;
                    const int b = r1 >> 11, srow = r1 & 2047;
                    *(float2*)&dst[(((size_t)b * HH + h) * SS + srow) * DD + d] = v1;
                }
            } else {
                *(float2*)&C[(size_t)r0 * N + c0] = v0;
                *(float2*)&C[(size_t)(r0 + 8) * N + c0] = v1;
            }
        }
    }
}

// ======================= Flash attention (fp32 SIMT, proven) ================
#define ATTN_SMEM_FLOATS (64 * 132 + 64 * 68 + 64 * 68 + 64 * 132 + 64)
#define ATTN_SMEM_BYTES (ATTN_SMEM_FLOATS * 4)

__global__ __launch_bounds__(256, 2) void attn_kernel(const int* __restrict__ att_mask) {
    extern __shared__ float smf[];
    float* Qs = smf;
    float* Ks = Qs + 64 * 132;
    float* Vs = Ks + 64 * 68;
    float* Ps = Vs + 64 * 68;
    int* msk = (int*)(Ps + 64 * 132);

    const int qt = (int)gridDim.x - 1 - (int)blockIdx.x;
    const int bh = blockIdx.y;
    const int b = bh / HH;
    const int h = bh % HH;
    const int tid = threadIdx.x;
    const int tx = tid & 15;
    const int ty = tid >> 4;
    const int q0 = qt * 128;

    const float* qptr = g_q + (size_t)bh * SS * DD;
    const float* kptr = g_k + (size_t)bh * SS * DD;
    const float* vptr = g_v + (size_t)bh * SS * DD;

#pragma unroll
    for (int it = 0; it < 8; it++) {
        int j = tid + it * 256;
        int q = j >> 4;
        int c4 = (j & 15) << 2;
        float4 v = *(const float4*)&qptr[(size_t)(q0 + q) * 64 + c4];
        Qs[(c4 + 0) * 132 + q] = v.x;
        Qs[(c4 + 1) * 132 + q] = v.y;
        Qs[(c4 + 2) * 132 + q] = v.z;
        Qs[(c4 + 3) * 132 + q] = v.w;
    }

    float o[8][4];
    float m[8], l[8];
#pragma unroll
    for (int i = 0; i < 8; i++) {
        m[i] = -1e30f;
        l[i] = 0.f;
#pragma unroll
        for (int j = 0; j < 4; j++) o[i][j] = 0.f;
    }

    const float SC = 0.125f * 1.4426950408889634f;
    const int ktmax = 2 * qt + 1;

    for (int kt = 0; kt <= ktmax; kt++) {
        __syncthreads();
#pragma unroll
        for (int it = 0; it < 4; it++) {
            int j = tid + it * 256;
            int r = j >> 4;
            int c4 = (j & 15) << 2;
            float4 kv = *(const float4*)&kptr[(size_t)(kt * 64 + r) * 64 + c4];
            Ks[(c4 + 0) * 68 + r] = kv.x;
            Ks[(c4 + 1) * 68 + r] = kv.y;
            Ks[(c4 + 2) * 68 + r] = kv.z;
            Ks[(c4 + 3) * 68 + r] = kv.w;
            *(float4*)&Vs[r * 68 + c4] = *(const float4*)&vptr[(size_t)(kt * 64 + r) * 64 + c4];
        }
        if (tid < 64) msk[tid] = att_mask[b * SS + kt * 64 + tid];
        __syncthreads();

        float s[8][4];
#pragma unroll
        for (int i = 0; i < 8; i++)
#pragma unroll
            for (int j = 0; j < 4; j++) s[i][j] = 0.f;
#pragma unroll 8
        for (int d = 0; d < 64; d++) {
            float a[8], bb[4];
            *(float4*)&a[0] = *(const float4*)&Qs[d * 132 + (ty << 3)];
            *(float4*)&a[4] = *(const float4*)&Qs[d * 132 + (ty << 3) + 4];
            *(float4*)&bb[0] = *(const float4*)&Ks[d * 68 + (tx << 2)];
#pragma unroll
            for (int i = 0; i < 8; i++)
#pragma unroll
                for (int j = 0; j < 4; j++) s[i][j] = fmaf(a[i], bb[j], s[i][j]);
        }

        const bool tileFull = (kt * 64 + 63) <= q0;
        float tb[4];
#pragma unroll
        for (int j = 0; j < 4; j++) tb[j] = msk[(tx << 2) + j] ? 0.f : -1e30f;

#pragma unroll
        for (int i = 0; i < 8; i++) {
            const int qg = q0 + (ty << 3) + i;
            float lm = -1e30f;
#pragma unroll
            for (int j = 0; j < 4; j++) {
                float tv = fmaf(s[i][j], SC, tb[j]);
                if (!tileFull && (kt * 64 + (tx << 2) + j) > qg) tv = -1e30f;
                s[i][j] = tv;
                lm = fmaxf(lm, tv);
            }
            lm = fmaxf(lm, __shfl_xor_sync(0xffffffffu, lm, 1));
            lm = fmaxf(lm, __shfl_xor_sync(0xffffffffu, lm, 2));
            lm = fmaxf(lm, __shfl_xor_sync(0xffffffffu, lm, 4));
            lm = fmaxf(lm, __shfl_xor_sync(0xffffffffu, lm, 8));
            float mn = fmaxf(m[i], lm);
            float alpha = fexp2(m[i] - mn);
            float ls = 0.f;
#pragma unroll
            for (int j = 0; j < 4; j++) {
                float p = fexp2(s[i][j] - mn);
                s[i][j] = p;
                ls += p;
            }
            ls += __shfl_xor_sync(0xffffffffu, ls, 1);
            ls += __shfl_xor_sync(0xffffffffu, ls, 2);
            ls += __shfl_xor_sync(0xffffffffu, ls, 4);
            ls += __shfl_xor_sync(0xffffffffu, ls, 8);
            l[i] = l[i] * alpha + ls;
            m[i] = mn;
#pragma unroll
            for (int j = 0; j < 4; j++) o[i][j] *= alpha;
        }

#pragma unroll
        for (int j = 0; j < 4; j++) {
            float4 lo = make_float4(s[0][j], s[1][j], s[2][j], s[3][j]);
            float4 hi = make_float4(s[4][j], s[5][j], s[6][j], s[7][j]);
            *(float4*)&Ps[((tx << 2) + j) * 132 + (ty << 3)] = lo;
            *(float4*)&Ps[((tx << 2) + j) * 132 + (ty << 3) + 4] = hi;
        }
        __syncthreads();

#pragma unroll 8
        for (int k = 0; k < 64; k++) {
            float a[8], bb[4];
            *(float4*)&a[0] = *(const float4*)&Ps[k * 132 + (ty << 3)];
            *(float4*)&a[4] = *(const float4*)&Ps[k * 132 + (ty << 3) + 4];
            *(float4*)&bb[0] = *(const float4*)&Vs[k * 68 + (tx << 2)];
#pragma unroll
            for (int i = 0; i < 8; i++)
#pragma unroll
                for (int j = 0; j < 4; j++) o[i][j] = fmaf(a[i], bb[j], o[i][j]);
        }
    }

#pragma unroll
    for (int i = 0; i < 8; i++) {
        float inv = 1.0f / l[i];
        int row = q0 + (ty << 3) + i;
        float4 w;
        w.x = o[i][0] * inv;
        w.y = o[i][1] * inv;
        w.z = o[i][2] * inv;
        w.w = o[i][3] * inv;
        *(float4*)&g_y[((size_t)b * SS + row) * EE + h * 64 + (tx << 2)] = w;
    }
}

// ---------------------------------------------------------------------------
extern "C" void kernel_launch(void* const* d_in, const int* in_sizes, int n_in,
                              void* d_out, int out_size) {
    const float* x = nullptr;
    const float* W_attn = nullptr;
    const float* b_attn = nullptr;
    const float* W_proj = nullptr;
    const float* b_proj = nullptr;
    const int* att_mask = nullptr;
    for (int i = 0; i < n_in; i++) {
        switch (in_sizes[i]) {
            case BB * SS * EE:   x = (const float*)d_in[i]; break;
            case EE * 3 * EE:    W_attn = (const float*)d_in[i]; break;
            case 3 * EE:         b_attn = (const float*)d_in[i]; break;
            case EE * EE:        W_proj = (const float*)d_in[i]; break;
            case EE:             b_proj = (const float*)d_in[i]; break;
            case BB * SS:        att_mask = (const int*)d_in[i]; break;
            default: break;
        }
    }
    float* out = (float*)d_out;

    static bool attr_set = false;
    if (!attr_set) {
        cudaFuncSetAttribute(attn_kernel, cudaFuncAttributeMaxDynamicSharedMemorySize,
                             ATTN_SMEM_BYTES);
        cudaFuncSetAttribute(gemm_mma<1>, cudaFuncAttributeMaxDynamicSharedMemorySize,
                             GEMM_SMEM);
        cudaFuncSetAttribute(gemm_mma<2>, cudaFuncAttributeMaxDynamicSharedMemorySize,
                             GEMM_SMEM);
        attr_set = true;
    }

    // 1) QKV GEMM (tf32 mma.sync) + scatter into [B,H,S,D]
    gemm_mma<1><<<dim3(3 * EE / 128, BB * SS / 128), 256, GEMM_SMEM>>>(
        x, W_attn, b_attn, nullptr, 3 * EE);

    // 2) Flash attention
    attn_kernel<<<dim3(SS / 128, BB * HH), 256, ATTN_SMEM_BYTES>>>(att_mask);

    // 3) Projection GEMM (tf32 mma.sync, reads g_y)
    gemm_mma<2><<<dim3(EE / 128, BB * SS / 128), 256, GEMM_SMEM>>>(
        nullptr, W_proj, b_proj, out, EE);
}

// round 7
// speedup vs baseline: 4.0157x; 1.6502x over previous
#include <cuda_runtime.h>
#include <math.h>
#include <cstdint>

#define BB 4
#define SS 2048
#define EE 768
#define HH 12
#define DD 64
#define GK 768

// Scratch (static device globals: no allocation allowed)
__device__ float g_q[(size_t)BB * HH * SS * DD];
__device__ float g_k[(size_t)BB * HH * SS * DD];
__device__ float g_v[(size_t)BB * HH * SS * DD];
__device__ float g_y[(size_t)BB * SS * EE];

// ======================= helpers ============================================
__device__ __forceinline__ uint32_t smem_u32(const void* p) {
    uint32_t a;
    asm("{ .reg .u64 t; cvta.to.shared.u64 t, %1; cvt.u32.u64 %0, t; }" : "=r"(a) : "l"(p));
    return a;
}
__device__ __forceinline__ void cp16(uint32_t dst, const void* src) {
    asm volatile("cp.async.cg.shared.global [%0], [%1], 16;" :: "r"(dst), "l"(src) : "memory");
}
__device__ __forceinline__ void cp_commit() {
    asm volatile("cp.async.commit_group;" ::: "memory");
}
template <int N>
__device__ __forceinline__ void cp_wait() {
    asm volatile("cp.async.wait_group %0;" :: "n"(N) : "memory");
}
__device__ __forceinline__ uint32_t f2tf32(float x) {
    uint32_t u;
    asm("cvt.rna.tf32.f32 %0, %1;" : "=r"(u) : "f"(x));
    return u;
}
__device__ __forceinline__ void mma_tf32(float* d, uint32_t a0, uint32_t a1, uint32_t a2,
                                         uint32_t a3, uint32_t b0, uint32_t b1) {
    asm volatile(
        "mma.sync.aligned.m16n8k8.row.col.f32.tf32.tf32.f32 "
        "{%0,%1,%2,%3}, {%4,%5,%6,%7}, {%8,%9}, {%0,%1,%2,%3};"
        : "+f"(d[0]), "+f"(d[1]), "+f"(d[2]), "+f"(d[3])
        : "r"(a0), "r"(a1), "r"(a2), "r"(a3), "r"(b0), "r"(b1));
}

// Fast exp2 on FMA pipe
__device__ __forceinline__ float fexp2(float x) {
    x = fmaxf(x, -126.f);
    float z = x + 12582912.f;
    int n = __float_as_int(z) - 0x4B400000;
    float fi = z - 12582912.f;
    float f = x - fi;
    float r = 1.3333558146e-3f;
    r = fmaf(r, f, 9.6181291e-3f);
    r = fmaf(r, f, 5.5504108664e-2f);
    r = fmaf(r, f, 2.4022650695910e-1f);
    r = fmaf(r, f, 6.9314718055995e-1f);
    r = fmaf(r, f, 1.0f);
    return r * __int_as_float((n + 127) << 23);
}

// ======================= tf32 mma.sync GEMM (unchanged, proven) =============
#define ABUF 18432            // 128*36*4
#define BBUF 17408            // 32*136*4
#define STAGE (ABUF + BBUF)   // 35840
#define GEMM_SMEM (2 * STAGE) // 71680

template <int MODE>
__global__ __launch_bounds__(256) void gemm_mma(const float* __restrict__ A_,
                                                const float* __restrict__ W,
                                                const float* __restrict__ bias,
                                                float* __restrict__ C, int N) {
    extern __shared__ char sm[];
    const uint32_t sbase = smem_u32(sm);

    const float* A = (MODE == 2) ? (const float*)g_y : A_;
    const int tid = threadIdx.x;
    const int wid = tid >> 5;
    const int lane = tid & 31;
    const int g = lane >> 2;
    const int t = lane & 3;
    const int bm = blockIdx.y * 128;
    const int bn = blockIdx.x * 128;
    const int wm = (wid >> 2) * 64;
    const int wn = (wid & 3) * 32;

    float acc[4][4][4];
#pragma unroll
    for (int mi = 0; mi < 4; mi++)
#pragma unroll
        for (int ni = 0; ni < 4; ni++)
#pragma unroll
            for (int r = 0; r < 4; r++) acc[mi][ni][r] = 0.f;

    const int am = tid >> 3;
    const int ac16 = (tid & 7) << 4;
    const int bk = tid >> 5;
    const int bn16 = (tid & 31) << 4;

#define ISSUE(s, buf)                                                                   \
    {                                                                                   \
        const int k0_ = (s) * 32;                                                       \
        const uint32_t sa_ = sbase + (buf) * STAGE;                                     \
        const uint32_t sb_ = sa_ + ABUF;                                                \
        _Pragma("unroll") for (int it = 0; it < 4; ++it) {                              \
            const int m_ = am + it * 32;                                                \
            cp16(sa_ + m_ * 144 + ac16, &A[(size_t)(bm + m_) * GK + k0_ + (ac16 >> 2)]);\
            const int k_ = bk + it * 8;                                                 \
            cp16(sb_ + k_ * 544 + bn16, &W[(size_t)(k0_ + k_) * N + bn + (bn16 >> 2)]); \
        }                                                                               \
        cp_commit();                                                                    \
    }

    ISSUE(0, 0);
    ISSUE(1, 1);

    for (int s = 0; s < 24; ++s) {
        const int buf = s & 1;
        if (s == 23) cp_wait<0>(); else cp_wait<1>();
        __syncthreads();

        const float* Af = (const float*)(sm + buf * STAGE);
        const float* Bf = (const float*)(sm + buf * STAGE + ABUF);

#pragma unroll
        for (int ks = 0; ks < 4; ++ks) {
            const int kk = ks * 8 + t;
            uint32_t b0[4], b1[4];
#pragma unroll
            for (int ni = 0; ni < 4; ++ni) {
                b0[ni] = f2tf32(Bf[kk * 136 + wn + ni * 8 + g]);
                b1[ni] = f2tf32(Bf[(kk + 4) * 136 + wn + ni * 8 + g]);
            }
#pragma unroll
            for (int mi = 0; mi < 4; ++mi) {
                const int r = wm + mi * 16 + g;
                uint32_t a0 = f2tf32(Af[r * 36 + kk]);
                uint32_t a1 = f2tf32(Af[(r + 8) * 36 + kk]);
                uint32_t a2 = f2tf32(Af[r * 36 + kk + 4]);
                uint32_t a3 = f2tf32(Af[(r + 8) * 36 + kk + 4]);
#pragma unroll
                for (int ni = 0; ni < 4; ++ni)
                    mma_tf32(acc[mi][ni], a0, a1, a2, a3, b0[ni], b1[ni]);
            }
        }
        __syncthreads();
        if (s + 2 < 24) ISSUE(s + 2, buf);
    }

#pragma unroll
    for (int mi = 0; mi < 4; ++mi) {
#pragma unroll
        for (int ni = 0; ni < 4; ++ni) {
            const int r0 = bm + wm + mi * 16 + g;
            const int c0 = bn + wn + ni * 8 + 2 * t;
            const float bz0 = __ldg(&bias[c0]);
            const float bz1 = __ldg(&bias[c0 + 1]);
            float2 v0 = make_float2(acc[mi][ni][0] + bz0, acc[mi][ni][1] + bz1);
            float2 v1 = make_float2(acc[mi][ni][2] + bz0, acc[mi][ni][3] + bz1);
            if (MODE == 1) {
                const int sec = c0 / EE;
                const int e = c0 - sec * EE;
                const int h = e >> 6, d = e & 63;
                float* dst = (sec == 0) ? g_q : ((sec == 1) ? g_k : g_v);
                {
                    const int b = r0 >> 11, srow = r0 & 2047;
                    *(float2*)&dst[(((size_t)b * HH + h) * SS + srow) * DD + d] = v0;
                }
                {
                    const int r1 = r0 + 8;
                    const int b = r1 >> 11, srow = r1 & 2047;
                    *(float2*)&dst[(((size_t)b * HH + h) * SS + srow) * DD + d] = v1;
                }
            } else {
                *(float2*)&C[(size_t)r0 * N + c0] = v0;
                *(float2*)&C[(size_t)(r0 + 8) * N + c0] = v1;
            }
        }
    }
}

// ======================= Flash attention via tf32 mma.sync ==================
// q-tile 128, k-tile 64, 256 threads / 8 warps; warp w owns q rows [16w,16w+16).
// Score: S = Q @ K^T  (A = Qs[q][d] row-major, B = Kt[d][key] "col-major").
// PV:    O += P @ V   (A = P via shuffle layout-convert, B = Vs[key][d]).
// Kt/Vs stride 72 -> all mma operand LDS conflict-free (bank = 8(t+ni)+g).
#define AQ_STR 68
#define KV_STR 72
#define ATTN_SMEM_FLOATS (128 * AQ_STR + 64 * KV_STR + 64 * KV_STR + 64)
#define ATTN_SMEM_BYTES (ATTN_SMEM_FLOATS * 4)

__global__ __launch_bounds__(256, 2) void attn_mma(const int* __restrict__ att_mask) {
    extern __shared__ float smf[];
    float* Qs = smf;                       // [q][d]  stride 68
    float* Kt = Qs + 128 * AQ_STR;         // [d][key] stride 72
    float* Vs = Kt + 64 * KV_STR;          // [key][d] stride 72
    int* msk = (int*)(Vs + 64 * KV_STR);

    const int qt = (int)gridDim.x - 1 - (int)blockIdx.x;
    const int bh = blockIdx.y;
    const int b = bh / HH;
    const int h = bh % HH;
    const int tid = threadIdx.x;
    const int wid = tid >> 5;
    const int lane = tid & 31;
    const int g = lane >> 2;
    const int t = lane & 3;
    const int q0 = qt * 128;

    const float* qptr = g_q + (size_t)bh * SS * DD;
    const float* kptr = g_k + (size_t)bh * SS * DD;
    const float* vptr = g_v + (size_t)bh * SS * DD;

    // Load Q tile [128][64] row-major
#pragma unroll
    for (int it = 0; it < 8; it++) {
        int j = tid + it * 256;
        int q = j >> 4;
        int c4 = (j & 15) << 2;
        *(float4*)&Qs[q * AQ_STR + c4] = *(const float4*)&qptr[(size_t)(q0 + q) * 64 + c4];
    }

    float ofrag[8][4];
#pragma unroll
    for (int nd = 0; nd < 8; nd++)
#pragma unroll
        for (int r = 0; r < 4; r++) ofrag[nd][r] = 0.f;
    float m0 = -1e30f, m1 = -1e30f, l0 = 0.f, l1 = 0.f;

    const float SC = 0.125f * 1.4426950408889634f;
    const int rowl = wid * 16 + g;         // local q row (frag row g)
    const int qg0 = q0 + rowl, qg1 = qg0 + 8;
    const int bl = lane & ~3;
    const int ktmax = 2 * qt + 1;

    // K transpose loader indices: lanes cover rows (conflict-free STS)
    const int krow = (lane & 31) + (wid & 1) * 32;      // 0..63
    const int kc4 = ((wid >> 1) << 2);                  // 0,4,8,12 (+16*it)

    for (int kt = 0; kt <= ktmax; kt++) {
        __syncthreads();
        // K transposed: Kt[d][key]
#pragma unroll
        for (int it = 0; it < 4; it++) {
            const int c4 = kc4 + it * 16;
            float4 kv = *(const float4*)&kptr[(size_t)(kt * 64 + krow) * 64 + c4];
            Kt[(c4 + 0) * KV_STR + krow] = kv.x;
            Kt[(c4 + 1) * KV_STR + krow] = kv.y;
            Kt[(c4 + 2) * KV_STR + krow] = kv.z;
            Kt[(c4 + 3) * KV_STR + krow] = kv.w;
        }
        // V straight: Vs[key][d]
#pragma unroll
        for (int it = 0; it < 4; it++) {
            int j = tid + it * 256;
            int r = j >> 4;
            int c4 = (j & 15) << 2;
            *(float4*)&Vs[r * KV_STR + c4] =
                *(const float4*)&vptr[(size_t)(kt * 64 + r) * 64 + c4];
        }
        if (tid < 64) msk[tid] = att_mask[b * SS + kt * 64 + tid];
        __syncthreads();

        // ---- scores: sf[ni][4] = S[m16][n64] frags ----
        float sf[8][4];
#pragma unroll
        for (int ni = 0; ni < 8; ni++)
#pragma unroll
            for (int r = 0; r < 4; r++) sf[ni][r] = 0.f;
#pragma unroll
        for (int dk = 0; dk < 8; dk++) {
            const int k0 = dk * 8;
            uint32_t a0 = f2tf32(Qs[rowl * AQ_STR + k0 + t]);
            uint32_t a1 = f2tf32(Qs[(rowl + 8) * AQ_STR + k0 + t]);
            uint32_t a2 = f2tf32(Qs[rowl * AQ_STR + k0 + t + 4]);
            uint32_t a3 = f2tf32(Qs[(rowl + 8) * AQ_STR + k0 + t + 4]);
#pragma unroll
            for (int ni = 0; ni < 8; ni++) {
                uint32_t b0 = f2tf32(Kt[(k0 + t) * KV_STR + ni * 8 + g]);
                uint32_t b1 = f2tf32(Kt[(k0 + t + 4) * KV_STR + ni * 8 + g]);
                mma_tf32(sf[ni], a0, a1, a2, a3, b0, b1);
            }
        }

        // ---- softmax (log2 domain) ----
        const bool tileFull = (kt * 64 + 63) <= q0;
        float mx0 = -1e30f, mx1 = -1e30f;
#pragma unroll
        for (int ni = 0; ni < 8; ni++) {
            const int cl0 = ni * 8 + 2 * t;
            const int cg0 = kt * 64 + cl0;
            const float tb0 = msk[cl0] ? 0.f : -1e30f;
            const float tb1 = msk[cl0 + 1] ? 0.f : -1e30f;
            float v00 = fmaf(sf[ni][0], SC, tb0);
            float v01 = fmaf(sf[ni][1], SC, tb1);
            float v10 = fmaf(sf[ni][2], SC, tb0);
            float v11 = fmaf(sf[ni][3], SC, tb1);
            if (!tileFull) {
                if (cg0 > qg0) v00 = -1e30f;
                if (cg0 + 1 > qg0) v01 = -1e30f;
                if (cg0 > qg1) v10 = -1e30f;
                if (cg0 + 1 > qg1) v11 = -1e30f;
            }
            sf[ni][0] = v00; sf[ni][1] = v01; sf[ni][2] = v10; sf[ni][3] = v11;
            mx0 = fmaxf(mx0, fmaxf(v00, v01));
            mx1 = fmaxf(mx1, fmaxf(v10, v11));
        }
        mx0 = fmaxf(mx0, __shfl_xor_sync(0xffffffffu, mx0, 1));
        mx0 = fmaxf(mx0, __shfl_xor_sync(0xffffffffu, mx0, 2));
        mx1 = fmaxf(mx1, __shfl_xor_sync(0xffffffffu, mx1, 1));
        mx1 = fmaxf(mx1, __shfl_xor_sync(0xffffffffu, mx1, 2));
        const float mn0 = fmaxf(m0, mx0), mn1 = fmaxf(m1, mx1);
        const float al0 = fexp2(m0 - mn0), al1 = fexp2(m1 - mn1);
        float s0 = 0.f, s1 = 0.f;
#pragma unroll
        for (int ni = 0; ni < 8; ni++) {
            sf[ni][0] = fexp2(sf[ni][0] - mn0);
            sf[ni][1] = fexp2(sf[ni][1] - mn0);
            sf[ni][2] = fexp2(sf[ni][2] - mn1);
            sf[ni][3] = fexp2(sf[ni][3] - mn1);
            s0 += sf[ni][0] + sf[ni][1];
            s1 += sf[ni][2] + sf[ni][3];
        }
        s0 += __shfl_xor_sync(0xffffffffu, s0, 1);
        s0 += __shfl_xor_sync(0xffffffffu, s0, 2);
        s1 += __shfl_xor_sync(0xffffffffu, s1, 1);
        s1 += __shfl_xor_sync(0xffffffffu, s1, 2);
        l0 = l0 * al0 + s0;
        l1 = l1 * al1 + s1;
        m0 = mn0;
        m1 = mn1;
#pragma unroll
        for (int nd = 0; nd < 8; nd++) {
            ofrag[nd][0] *= al0;
            ofrag[nd][1] *= al0;
            ofrag[nd][2] *= al1;
            ofrag[nd][3] *= al1;
        }

        // ---- PV: convert P acc-layout -> A-layout per k-chunk, then mma ----
        const int src0 = bl + (t >> 1);
        const int src1 = src0 + 2;
        const bool odd = (t & 1);
#pragma unroll
        for (int kc = 0; kc < 8; kc++) {
            float q00 = __shfl_sync(0xffffffffu, sf[kc][0], src0);
            float q01 = __shfl_sync(0xffffffffu, sf[kc][1], src0);
            float q10 = __shfl_sync(0xffffffffu, sf[kc][2], src0);
            float q11 = __shfl_sync(0xffffffffu, sf[kc][3], src0);
            float r00 = __shfl_sync(0xffffffffu, sf[kc][0], src1);
            float r01 = __shfl_sync(0xffffffffu, sf[kc][1], src1);
            float r10 = __shfl_sync(0xffffffffu, sf[kc][2], src1);
            float r11 = __shfl_sync(0xffffffffu, sf[kc][3], src1);
            uint32_t pa0 = f2tf32(odd ? q01 : q00);  // (g,   t)
            uint32_t pa1 = f2tf32(odd ? q11 : q10);  // (g+8, t)
            uint32_t pa2 = f2tf32(odd ? r01 : r00);  // (g,   t+4)
            uint32_t pa3 = f2tf32(odd ? r11 : r10);  // (g+8, t+4)
            const int kb = kc * 8;
#pragma unroll
            for (int nd = 0; nd < 8; nd++) {
                uint32_t b0 = f2tf32(Vs[(kb + t) * KV_STR + nd * 8 + g]);
                uint32_t b1 = f2tf32(Vs[(kb + t + 4) * KV_STR + nd * 8 + g]);
                mma_tf32(ofrag[nd], pa0, pa1, pa2, pa3, b0, b1);
            }
        }
    }

    // ---- epilogue ----
    const float inv0 = 1.0f / l0, inv1 = 1.0f / l1;
    const int r0 = q0 + rowl, r1 = r0 + 8;
#pragma unroll
    for (int nd = 0; nd < 8; nd++) {
        const int c0 = nd * 8 + 2 * t;
        float2 v0 = make_float2(ofrag[nd][0] * inv0, ofrag[nd][1] * inv0);
        float2 v1 = make_float2(ofrag[nd][2] * inv1, ofrag[nd][3] * inv1);
        *(float2*)&g_y[((size_t)b * SS + r0) * EE + h * 64 + c0] = v0;
        *(float2*)&g_y[((size_t)b * SS + r1) * EE + h * 64 + c0] = v1;
    }
}

// ---------------------------------------------------------------------------
extern "C" void kernel_launch(void* const* d_in, const int* in_sizes, int n_in,
                              void* d_out, int out_size) {
    const float* x = nullptr;
    const float* W_attn = nullptr;
    const float* b_attn = nullptr;
    const float* W_proj = nullptr;
    const float* b_proj = nullptr;
    const int* att_mask = nullptr;
    for (int i = 0; i < n_in; i++) {
        switch (in_sizes[i]) {
            case BB * SS * EE:   x = (const float*)d_in[i]; break;
            case EE * 3 * EE:    W_attn = (const float*)d_in[i]; break;
            case 3 * EE:         b_attn = (const float*)d_in[i]; break;
            case EE * EE:        W_proj = (const float*)d_in[i]; break;
            case EE:             b_proj = (const float*)d_in[i]; break;
            case BB * SS:        att_mask = (const int*)d_in[i]; break;
            default: break;
        }
    }
    float* out = (float*)d_out;

    static bool attr_set = false;
    if (!attr_set) {
        cudaFuncSetAttribute(attn_mma, cudaFuncAttributeMaxDynamicSharedMemorySize,
                             ATTN_SMEM_BYTES);
        cudaFuncSetAttribute(gemm_mma<1>, cudaFuncAttributeMaxDynamicSharedMemorySize,
                             GEMM_SMEM);
        cudaFuncSetAttribute(gemm_mma<2>, cudaFuncAttributeMaxDynamicSharedMemorySize,
                             GEMM_SMEM);
        attr_set = true;
    }

    // 1) QKV GEMM (tf32 mma.sync) + scatter into [B,H,S,D]
    gemm_mma<1><<<dim3(3 * EE / 128, BB * SS / 128), 256, GEMM_SMEM>>>(
        x, W_attn, b_attn, nullptr, 3 * EE);

    // 2) Flash attention (tf32 mma.sync)
    attn_mma<<<dim3(SS / 128, BB * HH), 256, ATTN_SMEM_BYTES>>>(att_mask);

    // 3) Projection GEMM (tf32 mma.sync, reads g_y)
    gemm_mma<2><<<dim3(EE / 128, BB * SS / 128), 256, GEMM_SMEM>>>(
        nullptr, W_proj, b_proj, out, EE);
}

// round 9
// speedup vs baseline: 4.4361x; 1.1047x over previous
#include <cuda_runtime.h>
#include <math.h>
#include <cstdint>

#define BB 4
#define SS 2048
#define EE 768
#define HH 12
#define DD 64
#define GK 768

// Scratch (static device globals: no allocation allowed)
// g_q/g_k/g_v/g_y hold tf32-rounded bit patterns (still valid floats).
__device__ float g_q[(size_t)BB * HH * SS * DD];
__device__ float g_k[(size_t)BB * HH * SS * DD];
__device__ float g_v[(size_t)BB * HH * SS * DD];
__device__ float g_y[(size_t)BB * SS * EE];
__device__ uint32_t g_xt[(size_t)BB * SS * EE];    // x -> tf32 bits
__device__ uint32_t g_wat[(size_t)EE * 3 * EE];    // W_attn -> tf32 bits
__device__ uint32_t g_wpt[(size_t)EE * EE];        // W_proj -> tf32 bits

// ======================= helpers ============================================
__device__ __forceinline__ uint32_t smem_u32(const void* p) {
    uint32_t a;
    asm("{ .reg .u64 t; cvta.to.shared.u64 t, %1; cvt.u32.u64 %0, t; }" : "=r"(a) : "l"(p));
    return a;
}
__device__ __forceinline__ void cp16(uint32_t dst, const void* src) {
    asm volatile("cp.async.cg.shared.global [%0], [%1], 16;" :: "r"(dst), "l"(src) : "memory");
}
__device__ __forceinline__ void cp_commit() {
    asm volatile("cp.async.commit_group;" ::: "memory");
}
template <int N>
__device__ __forceinline__ void cp_wait() {
    asm volatile("cp.async.wait_group %0;" :: "n"(N) : "memory");
}
__device__ __forceinline__ uint32_t f2tf32(float x) {
    uint32_t u;
    asm("cvt.rna.tf32.f32 %0, %1;" : "=r"(u) : "f"(x));
    return u;
}
__device__ __forceinline__ void mma_tf32(float* d, uint32_t a0, uint32_t a1, uint32_t a2,
                                         uint32_t a3, uint32_t b0, uint32_t b1) {
    asm volatile(
        "mma.sync.aligned.m16n8k8.row.col.f32.tf32.tf32.f32 "
        "{%0,%1,%2,%3}, {%4,%5,%6,%7}, {%8,%9}, {%0,%1,%2,%3};"
        : "+f"(d[0]), "+f"(d[1]), "+f"(d[2]), "+f"(d[3])
        : "r"(a0), "r"(a1), "r"(a2), "r"(a3), "r"(b0), "r"(b1));
}

// Fast exp2 on FMA pipe
__device__ __forceinline__ float fexp2(float x) {
    x = fmaxf(x, -126.f);
    float z = x + 12582912.f;
    int n = __float_as_int(z) - 0x4B400000;
    float fi = z - 12582912.f;
    float f = x - fi;
    float r = 1.3333558146e-3f;
    r = fmaf(r, f, 9.6181291e-3f);
    r = fmaf(r, f, 5.5504108664e-2f);
    r = fmaf(r, f, 2.4022650695910e-1f);
    r = fmaf(r, f, 6.9314718055995e-1f);
    r = fmaf(r, f, 1.0f);
    return r * __int_as_float((n + 127) << 23);
}

// ======================= fp32 -> tf32 bit pre-pass ==========================
__global__ void cvt_tf32_kernel(const float4* __restrict__ src, uint4* __restrict__ dst,
                                int n4) {
    int i = blockIdx.x * blockDim.x + threadIdx.x;
    if (i < n4) {
        float4 v = src[i];
        dst[i] = make_uint4(f2tf32(v.x), f2tf32(v.y), f2tf32(v.z), f2tf32(v.w));
    }
}

// ======================= tf32 mma.sync GEMM =================================
// Inputs A/W are PRE-CONVERTED tf32 bit arrays; mainloop has zero cvt.
#define ABUF 18432            // 128*36*4
#define BBUF 17408            // 32*136*4
#define STAGE (ABUF + BBUF)   // 35840
#define GEMM_SMEM (2 * STAGE) // 71680

template <int MODE>
__global__ __launch_bounds__(256) void gemm_mma(const uint32_t* __restrict__ A_,
                                                const uint32_t* __restrict__ W,
                                                const float* __restrict__ bias,
                                                float* __restrict__ C, int N) {
    extern __shared__ char sm[];
    const uint32_t sbase = smem_u32(sm);

    const uint32_t* A = (MODE == 2) ? (const uint32_t*)g_y : A_;
    const int tid = threadIdx.x;
    const int wid = tid >> 5;
    const int lane = tid & 31;
    const int g = lane >> 2;
    const int t = lane & 3;
    const int bm = blockIdx.y * 128;
    const int bn = blockIdx.x * 128;
    const int wm = (wid >> 2) * 64;
    const int wn = (wid & 3) * 32;

    float acc[4][4][4];
#pragma unroll
    for (int mi = 0; mi < 4; mi++)
#pragma unroll
        for (int ni = 0; ni < 4; ni++)
#pragma unroll
            for (int r = 0; r < 4; r++) acc[mi][ni][r] = 0.f;

    const int am = tid >> 3;
    const int ac16 = (tid & 7) << 4;
    const int bk = tid >> 5;
    const int bn16 = (tid & 31) << 4;

#define ISSUE(s, buf)                                                                   \
    {                                                                                   \
        const int k0_ = (s) * 32;                                                       \
        const uint32_t sa_ = sbase + (buf) * STAGE;                                     \
        const uint32_t sb_ = sa_ + ABUF;                                                \
        _Pragma("unroll") for (int it = 0; it < 4; ++it) {                              \
            const int m_ = am + it * 32;                                                \
            cp16(sa_ + m_ * 144 + ac16, &A[(size_t)(bm + m_) * GK + k0_ + (ac16 >> 2)]);\
            const int k_ = bk + it * 8;                                                 \
            cp16(sb_ + k_ * 544 + bn16, &W[(size_t)(k0_ + k_) * N + bn + (bn16 >> 2)]); \
        }                                                                               \
        cp_commit();                                                                    \
    }

    ISSUE(0, 0);
    ISSUE(1, 1);

    for (int s = 0; s < 24; ++s) {
        const int buf = s & 1;
        if (s == 23) cp_wait<0>(); else cp_wait<1>();
        __syncthreads();

        const uint32_t* Af = (const uint32_t*)(sm + buf * STAGE);
        const uint32_t* Bf = (const uint32_t*)(sm + buf * STAGE + ABUF);

#pragma unroll
        for (int ks = 0; ks < 4; ++ks) {
            const int kk = ks * 8 + t;
            uint32_t b0[4], b1[4];
#pragma unroll
            for (int ni = 0; ni < 4; ++ni) {
                b0[ni] = Bf[kk * 136 + wn + ni * 8 + g];
                b1[ni] = Bf[(kk + 4) * 136 + wn + ni * 8 + g];
            }
#pragma unroll
            for (int mi = 0; mi < 4; ++mi) {
                const int r = wm + mi * 16 + g;
                uint32_t a0 = Af[r * 36 + kk];
                uint32_t a1 = Af[(r + 8) * 36 + kk];
                uint32_t a2 = Af[r * 36 + kk + 4];
                uint32_t a3 = Af[(r + 8) * 36 + kk + 4];
#pragma unroll
                for (int ni = 0; ni < 4; ++ni)
                    mma_tf32(acc[mi][ni], a0, a1, a2, a3, b0[ni], b1[ni]);
            }
        }
        __syncthreads();
        if (s + 2 < 24) ISSUE(s + 2, buf);
    }

#pragma unroll
    for (int mi = 0; mi < 4; ++mi) {
#pragma unroll
        for (int ni = 0; ni < 4; ++ni) {
            const int r0 = bm + wm + mi * 16 + g;
            const int c0 = bn + wn + ni * 8 + 2 * t;
            const float bz0 = __ldg(&bias[c0]);
            const float bz1 = __ldg(&bias[c0 + 1]);
            if (MODE == 1) {
                // Write Q/K/V pre-rounded to tf32 (same rounding the attention
                // mma would apply on read -> zero extra error).
                float2 v0 = make_float2(
                    __uint_as_float(f2tf32(acc[mi][ni][0] + bz0)),
                    __uint_as_float(f2tf32(acc[mi][ni][1] + bz1)));
                float2 v1 = make_float2(
                    __uint_as_float(f2tf32(acc[mi][ni][2] + bz0)),
                    __uint_as_float(f2tf32(acc[mi][ni][3] + bz1)));
                const int sec = c0 / EE;
                const int e = c0 - sec * EE;
                const int h = e >> 6, d = e & 63;
                float* dst = (sec == 0) ? g_q : ((sec == 1) ? g_k : g_v);
                {
                    const int b = r0 >> 11, srow = r0 & 2047;
                    *(float2*)&dst[(((size_t)b * HH + h) * SS + srow) * DD + d] = v0;
                }
                {
                    const int r1 = r0 + 8;
                    const int b = r1 >> 11, srow = r1 & 2047;
                    *(float2*)&dst[(((size_t)b * HH + h) * SS + srow) * DD + d] = v1;
                }
            } else {
                float2 v0 = make_float2(acc[mi][ni][0] + bz0, acc[mi][ni][1] + bz1);
                float2 v1 = make_float2(acc[mi][ni][2] + bz0, acc[mi][ni][3] + bz1);
                *(float2*)&C[(size_t)r0 * N + c0] = v0;
                *(float2*)&C[(size_t)(r0 + 8) * N + c0] = v1;
            }
        }
    }
}

// ======================= Flash attention via tf32 mma.sync ==================
// Q/K/V arrive as tf32 bit patterns; smem loads are raw copies, mma operands
// are free reinterprets. Only P (post-exp) needs cvt.
#define AQ_STR 68
#define KV_STR 72
#define ATTN_SMEM_FLOATS (128 * AQ_STR + 64 * KV_STR + 64 * KV_STR + 64)
#define ATTN_SMEM_BYTES (ATTN_SMEM_FLOATS * 4)

__global__ __launch_bounds__(256, 2) void attn_mma(const int* __restrict__ att_mask) {
    extern __shared__ float smf[];
    float* Qs = smf;                       // [q][d]  stride 68
    float* Kt = Qs + 128 * AQ_STR;         // [d][key] stride 72
    float* Vs = Kt + 64 * KV_STR;          // [key][d] stride 72
    int* msk = (int*)(Vs + 64 * KV_STR);

    const int qt = (int)gridDim.x - 1 - (int)blockIdx.x;
    const int bh = blockIdx.y;
    const int b = bh / HH;
    const int h = bh % HH;
    const int tid = threadIdx.x;
    const int wid = tid >> 5;
    const int lane = tid & 31;
    const int g = lane >> 2;
    const int t = lane & 3;
    const int q0 = qt * 128;

    const float* qptr = g_q + (size_t)bh * SS * DD;
    const float* kptr = g_k + (size_t)bh * SS * DD;
    const float* vptr = g_v + (size_t)bh * SS * DD;

#pragma unroll
    for (int it = 0; it < 8; it++) {
        int j = tid + it * 256;
        int q = j >> 4;
        int c4 = (j & 15) << 2;
        *(float4*)&Qs[q * AQ_STR + c4] = *(const float4*)&qptr[(size_t)(q0 + q) * 64 + c4];
    }

    float ofrag[8][4];
#pragma unroll
    for (int nd = 0; nd < 8; nd++)
#pragma unroll
        for (int r = 0; r < 4; r++) ofrag[nd][r] = 0.f;
    float m0 = -1e30f, m1 = -1e30f, l0 = 0.f, l1 = 0.f;

    const float SC = 0.125f * 1.4426950408889634f;
    const int rowl = wid * 16 + g;
    const int qg0 = q0 + rowl, qg1 = qg0 + 8;
    const int bl = lane & ~3;
    const int ktmax = 2 * qt + 1;

    const int krow = (lane & 31) + (wid & 1) * 32;
    const int kc4 = ((wid >> 1) << 2);

    for (int kt = 0; kt <= ktmax; kt++) {
        __syncthreads();
#pragma unroll
        for (int it = 0; it < 4; it++) {
            const int c4 = kc4 + it * 16;
            float4 kv = *(const float4*)&kptr[(size_t)(kt * 64 + krow) * 64 + c4];
            Kt[(c4 + 0) * KV_STR + krow] = kv.x;
            Kt[(c4 + 1) * KV_STR + krow] = kv.y;
            Kt[(c4 + 2) * KV_STR + krow] = kv.z;
            Kt[(c4 + 3) * KV_STR + krow] = kv.w;
        }
#pragma unroll
        for (int it = 0; it < 4; it++) {
            int j = tid + it * 256;
            int r = j >> 4;
            int c4 = (j & 15) << 2;
            *(float4*)&Vs[r * KV_STR + c4] =
                *(const float4*)&vptr[(size_t)(kt * 64 + r) * 64 + c4];
        }
        if (tid < 64) msk[tid] = att_mask[b * SS + kt * 64 + tid];
        __syncthreads();

        // ---- scores ----
        float sf[8][4];
#pragma unroll
        for (int ni = 0; ni < 8; ni++)
#pragma unroll
            for (int r = 0; r < 4; r++) sf[ni][r] = 0.f;
#pragma unroll
        for (int dk = 0; dk < 8; dk++) {
            const int k0 = dk * 8;
            uint32_t a0 = __float_as_uint(Qs[rowl * AQ_STR + k0 + t]);
            uint32_t a1 = __float_as_uint(Qs[(rowl + 8) * AQ_STR + k0 + t]);
            uint32_t a2 = __float_as_uint(Qs[rowl * AQ_STR + k0 + t + 4]);
            uint32_t a3 = __float_as_uint(Qs[(rowl + 8) * AQ_STR + k0 + t + 4]);
#pragma unroll
            for (int ni = 0; ni < 8; ni++) {
                uint32_t b0 = __float_as_uint(Kt[(k0 + t) * KV_STR + ni * 8 + g]);
                uint32_t b1 = __float_as_uint(Kt[(k0 + t + 4) * KV_STR + ni * 8 + g]);
                mma_tf32(sf[ni], a0, a1, a2, a3, b0, b1);
            }
        }

        // ---- softmax (log2 domain) ----
        const bool tileFull = (kt * 64 + 63) <= q0;
        float mx0 = -1e30f, mx1 = -1e30f;
#pragma unroll
        for (int ni = 0; ni < 8; ni++) {
            const int cl0 = ni * 8 + 2 * t;
            const int cg0 = kt * 64 + cl0;
            const float tb0 = msk[cl0] ? 0.f : -1e30f;
            const float tb1 = msk[cl0 + 1] ? 0.f : -1e30f;
            float v00 = fmaf(sf[ni][0], SC, tb0);
            float v01 = fmaf(sf[ni][1], SC, tb1);
            float v10 = fmaf(sf[ni][2], SC, tb0);
            float v11 = fmaf(sf[ni][3], SC, tb1);
            if (!tileFull) {
                if (cg0 > qg0) v00 = -1e30f;
                if (cg0 + 1 > qg0) v01 = -1e30f;
                if (cg0 > qg1) v10 = -1e30f;
                if (cg0 + 1 > qg1) v11 = -1e30f;
            }
            sf[ni][0] = v00; sf[ni][1] = v01; sf[ni][2] = v10; sf[ni][3] = v11;
            mx0 = fmaxf(mx0, fmaxf(v00, v01));
            mx1 = fmaxf(mx1, fmaxf(v10, v11));
        }
        mx0 = fmaxf(mx0, __shfl_xor_sync(0xffffffffu, mx0, 1));
        mx0 = fmaxf(mx0, __shfl_xor_sync(0xffffffffu, mx0, 2));
        mx1 = fmaxf(mx1, __shfl_xor_sync(0xffffffffu, mx1, 1));
        mx1 = fmaxf(mx1, __shfl_xor_sync(0xffffffffu, mx1, 2));
        const float mn0 = fmaxf(m0, mx0), mn1 = fmaxf(m1, mx1);
        const float al0 = fexp2(m0 - mn0), al1 = fexp2(m1 - mn1);
        float s0 = 0.f, s1 = 0.f;
#pragma unroll
        for (int ni = 0; ni < 8; ni++) {
            sf[ni][0] = fexp2(sf[ni][0] - mn0);
            sf[ni][1] = fexp2(sf[ni][1] - mn0);
            sf[ni][2] = fexp2(sf[ni][2] - mn1);
            sf[ni][3] = fexp2(sf[ni][3] - mn1);
            s0 += sf[ni][0] + sf[ni][1];
            s1 += sf[ni][2] + sf[ni][3];
        }
        s0 += __shfl_xor_sync(0xffffffffu, s0, 1);
        s0 += __shfl_xor_sync(0xffffffffu, s0, 2);
        s1 += __shfl_xor_sync(0xffffffffu, s1, 1);
        s1 += __shfl_xor_sync(0xffffffffu, s1, 2);
        l0 = l0 * al0 + s0;
        l1 = l1 * al1 + s1;
        m0 = mn0;
        m1 = mn1;
#pragma unroll
        for (int nd = 0; nd < 8; nd++) {
            ofrag[nd][0] *= al0;
            ofrag[nd][1] *= al0;
            ofrag[nd][2] *= al1;
            ofrag[nd][3] *= al1;
        }

        // ---- PV ----
        const int src0 = bl + (t >> 1);
        const int src1 = src0 + 2;
        const bool odd = (t & 1);
#pragma unroll
        for (int kc = 0; kc < 8; kc++) {
            float q00 = __shfl_sync(0xffffffffu, sf[kc][0], src0);
            float q01 = __shfl_sync(0xffffffffu, sf[kc][1], src0);
            float q10 = __shfl_sync(0xffffffffu, sf[kc][2], src0);
            float q11 = __shfl_sync(0xffffffffu, sf[kc][3], src0);
            float r00 = __shfl_sync(0xffffffffu, sf[kc][0], src1);
            float r01 = __shfl_sync(0xffffffffu, sf[kc][1], src1);
            float r10 = __shfl_sync(0xffffffffu, sf[kc][2], src1);
            float r11 = __shfl_sync(0xffffffffu, sf[kc][3], src1);
            uint32_t pa0 = f2tf32(odd ? q01 : q00);
            uint32_t pa1 = f2tf32(odd ? q11 : q10);
            uint32_t pa2 = f2tf32(odd ? r01 : r00);
            uint32_t pa3 = f2tf32(odd ? r11 : r10);
            const int kb = kc * 8;
#pragma unroll
            for (int nd = 0; nd < 8; nd++) {
                uint32_t b0 = __float_as_uint(Vs[(kb + t) * KV_STR + nd * 8 + g]);
                uint32_t b1 = __float_as_uint(Vs[(kb + t + 4) * KV_STR + nd * 8 + g]);
                mma_tf32(ofrag[nd], pa0, pa1, pa2, pa3, b0, b1);
            }
        }
    }

    // ---- epilogue: write g_y pre-rounded to tf32 (gemm2's A operand) ----
    const float inv0 = 1.0f / l0, inv1 = 1.0f / l1;
    const int r0 = q0 + rowl, r1 = r0 + 8;
#pragma unroll
    for (int nd = 0; nd < 8; nd++) {
        const int c0 = nd * 8 + 2 * t;
        float2 v0 = make_float2(__uint_as_float(f2tf32(ofrag[nd][0] * inv0)),
                                __uint_as_float(f2tf32(ofrag[nd][1] * inv0)));
        float2 v1 = make_float2(__uint_as_float(f2tf32(ofrag[nd][2] * inv1)),
                                __uint_as_float(f2tf32(ofrag[nd][3] * inv1)));
        *(float2*)&g_y[((size_t)b * SS + r0) * EE + h * 64 + c0] = v0;
        *(float2*)&g_y[((size_t)b * SS + r1) * EE + h * 64 + c0] = v1;
    }
}

// ---------------------------------------------------------------------------
extern "C" void kernel_launch(void* const* d_in, const int* in_sizes, int n_in,
                              void* d_out, int out_size) {
    const float* x = nullptr;
    const float* W_attn = nullptr;
    const float* b_attn = nullptr;
    const float* W_proj = nullptr;
    const float* b_proj = nullptr;
    const int* att_mask = nullptr;
    for (int i = 0; i < n_in; i++) {
        switch (in_sizes[i]) {
            case BB * SS * EE:   x = (const float*)d_in[i]; break;
            case EE * 3 * EE:    W_attn = (const float*)d_in[i]; break;
            case 3 * EE:         b_attn = (const float*)d_in[i]; break;
            case EE * EE:        W_proj = (const float*)d_in[i]; break;
            case EE:             b_proj = (const float*)d_in[i]; break;
            case BB * SS:        att_mask = (const int*)d_in[i]; break;
            default: break;
        }
    }
    float* out = (float*)d_out;

    static bool attr_set = false;
    if (!attr_set) {
        cudaFuncSetAttribute(attn_mma, cudaFuncAttributeMaxDynamicSharedMemorySize,
                             ATTN_SMEM_BYTES);
        cudaFuncSetAttribute(gemm_mma<1>, cudaFuncAttributeMaxDynamicSharedMemorySize,
                             GEMM_SMEM);
        cudaFuncSetAttribute(gemm_mma<2>, cudaFuncAttributeMaxDynamicSharedMemorySize,
                             GEMM_SMEM);
        attr_set = true;
    }

    uint32_t *xt, *wat, *wpt;
    cudaGetSymbolAddress((void**)&xt, g_xt);
    cudaGetSymbolAddress((void**)&wat, g_wat);
    cudaGetSymbolAddress((void**)&wpt, g_wpt);

    // 0) Pre-convert inputs to tf32 bit arrays (rounding points identical to
    //    the per-read cvt they replace).
    {
        int n4;
        n4 = BB * SS * EE / 4;
        cvt_tf32_kernel<<<(n4 + 255) / 256, 256>>>((const float4*)x, (uint4*)xt, n4);
        n4 = EE * 3 * EE / 4;
        cvt_tf32_kernel<<<(n4 + 255) / 256, 256>>>((const float4*)W_attn, (uint4*)wat, n4);
        n4 = EE * EE / 4;
        cvt_tf32_kernel<<<(n4 + 255) / 256, 256>>>((const float4*)W_proj, (uint4*)wpt, n4);
    }

    // 1) QKV GEMM (tf32 mma.sync, cvt-free mainloop) + tf32-rounded scatter
    gemm_mma<1><<<dim3(3 * EE / 128, BB * SS / 128), 256, GEMM_SMEM>>>(
        xt, wat, b_attn, nullptr, 3 * EE);

    // 2) Flash attention (tf32 mma.sync, cvt-free operand path)
    attn_mma<<<dim3(SS / 128, BB * HH), 256, ATTN_SMEM_BYTES>>>(att_mask);

    // 3) Projection GEMM (reads tf32-rounded g_y)
    gemm_mma<2><<<dim3(EE / 128, BB * SS / 128), 256, GEMM_SMEM>>>(
        nullptr, wpt, b_proj, out, EE);
}